// round 1
// baseline (speedup 1.0000x reference)
#include <cuda_runtime.h>
#include <cstdint>

#define NTHREADS 256
#define EPT 2   // elements per thread

__device__ __forceinline__ unsigned long long fma2(unsigned long long a,
                                                   unsigned long long b,
                                                   unsigned long long c) {
    unsigned long long d;
    asm("fma.rn.f32x2 %0, %1, %2, %3;" : "=l"(d) : "l"(a), "l"(b), "l"(c));
    return d;
}

__device__ __forceinline__ unsigned long long mul2(unsigned long long a,
                                                   unsigned long long b) {
    unsigned long long d;
    asm("mul.rn.f32x2 %0, %1, %2;" : "=l"(d) : "l"(a), "l"(b));
    return d;
}

// x = [u*m, u, m] (96) ; h = relu(x @ w1^T + b1) (8) ; out = sigmoid(h @ w2^T + b2)
// w1 is [8][96] row-major: cols 0..31 = A (um), 32..63 = B (u), 64..95 = C (m).
// SMEM restage: sw1[jp][comp][i][t] with 48 floats per factor-pair jp so each jp's
// weights arrive via 12x LDS.128 (2 f32x2 operands per load).
__global__ __launch_bounds__(NTHREADS)
void neuralnet_fwd_kernel(const int* __restrict__ users,
                          const int* __restrict__ movies,
                          const float* __restrict__ user_emb,
                          const float* __restrict__ movie_emb,
                          const float* __restrict__ w1,
                          const float* __restrict__ b1,
                          const float* __restrict__ w2,
                          const float* __restrict__ b2,
                          float* __restrict__ out,
                          int n) {
    __shared__ __align__(16) float sw1[768];
    __shared__ float sb1[8];
    __shared__ float sw2[8];
    __shared__ float sb2;

    const int tid = threadIdx.x;

    // Restage w1: sw1[jp*48 + comp*16 + i*2 + t] = w1[i*96 + comp*32 + 2*jp + t]
    for (int L = tid; L < 768; L += NTHREADS) {
        int jp   = L / 48;
        int r    = L - jp * 48;
        int comp = r >> 4;
        int q    = r & 15;
        int i    = q >> 1;
        int t    = q & 1;
        sw1[L] = w1[i * 96 + comp * 32 + 2 * jp + t];
    }
    if (tid < 8) { sb1[tid] = b1[tid]; sw2[tid] = w2[tid]; }
    if (tid == 0) sb2 = b2[0];
    __syncthreads();

    int idx0 = blockIdx.x * (NTHREADS * EPT) + tid;
    int idx1 = idx0 + NTHREADS;
    if (idx0 >= n) return;
    bool have1 = (idx1 < n);
    int idx1c = have1 ? idx1 : idx0;   // duplicate work on ragged tail (store guarded)

    const ulonglong2* up0 =
        (const ulonglong2*)(user_emb + (size_t)users[idx0] * 32);
    const ulonglong2* mp0 =
        (const ulonglong2*)(movie_emb + (size_t)movies[idx0] * 32);
    const ulonglong2* up1 =
        (const ulonglong2*)(user_emb + (size_t)users[idx1c] * 32);
    const ulonglong2* mp1 =
        (const ulonglong2*)(movie_emb + (size_t)movies[idx1c] * 32);

    unsigned long long acc0[8], acc1[8];
#pragma unroll
    for (int i = 0; i < 8; i++) { acc0[i] = 0ull; acc1[i] = 0ull; }

#pragma unroll 4
    for (int q = 0; q < 8; ++q) {   // one float4-quad = 2 factor-pairs
        ulonglong2 ua = up0[q], ma = mp0[q];
        ulonglong2 ub = up1[q], mb = mp1[q];
#pragma unroll
        for (int s = 0; s < 2; ++s) {
            int jp = 2 * q + s;
            unsigned long long u0 = s ? ua.y : ua.x;
            unsigned long long m0 = s ? ma.y : ma.x;
            unsigned long long u1 = s ? ub.y : ub.x;
            unsigned long long m1 = s ? mb.y : mb.x;
            unsigned long long um0 = mul2(u0, m0);
            unsigned long long um1 = mul2(u1, m1);

            const ulonglong2* wq = (const ulonglong2*)(&sw1[jp * 48]);
            unsigned long long wA[8], wB[8], wC[8];
#pragma unroll
            for (int p = 0; p < 4; p++) {
                ulonglong2 v = wq[p];
                wA[2 * p] = v.x; wA[2 * p + 1] = v.y;
            }
#pragma unroll
            for (int p = 0; p < 4; p++) {
                ulonglong2 v = wq[4 + p];
                wB[2 * p] = v.x; wB[2 * p + 1] = v.y;
            }
#pragma unroll
            for (int p = 0; p < 4; p++) {
                ulonglong2 v = wq[8 + p];
                wC[2 * p] = v.x; wC[2 * p + 1] = v.y;
            }
#pragma unroll
            for (int i = 0; i < 8; i++) {
                acc0[i] = fma2(wA[i], um0, acc0[i]);
                acc0[i] = fma2(wB[i], u0, acc0[i]);
                acc0[i] = fma2(wC[i], m0, acc0[i]);
                acc1[i] = fma2(wA[i], um1, acc1[i]);
                acc1[i] = fma2(wB[i], u1, acc1[i]);
                acc1[i] = fma2(wC[i], m1, acc1[i]);
            }
        }
    }

    // Epilogue: horizontal add of pair lanes, bias, relu, 8-dot, sigmoid.
    float z0 = sb2, z1 = sb2;
#pragma unroll
    for (int i = 0; i < 8; i++) {
        float2 a0 = *(float2*)&acc0[i];
        float2 a1 = *(float2*)&acc1[i];
        float h0 = fmaxf(a0.x + a0.y + sb1[i], 0.0f);
        float h1 = fmaxf(a1.x + a1.y + sb1[i], 0.0f);
        z0 = fmaf(h0, sw2[i], z0);
        z1 = fmaf(h1, sw2[i], z1);
    }
    out[idx0] = 1.0f / (1.0f + __expf(-z0));
    if (have1) out[idx1] = 1.0f / (1.0f + __expf(-z1));
}

extern "C" void kernel_launch(void* const* d_in, const int* in_sizes, int n_in,
                              void* d_out, int out_size) {
    const int*   users     = (const int*)d_in[0];
    const int*   movies    = (const int*)d_in[1];
    const float* user_emb  = (const float*)d_in[2];
    const float* movie_emb = (const float*)d_in[3];
    const float* w1        = (const float*)d_in[4];
    const float* b1        = (const float*)d_in[5];
    const float* w2        = (const float*)d_in[6];
    const float* b2        = (const float*)d_in[7];
    int n = in_sizes[0];

    int blocks = (n + NTHREADS * EPT - 1) / (NTHREADS * EPT);
    neuralnet_fwd_kernel<<<blocks, NTHREADS>>>(
        users, movies, user_emb, movie_emb, w1, b1, w2, b2, (float*)d_out, n);
}

// round 3
// speedup vs baseline: 1.1667x; 1.1667x over previous
#include <cuda_runtime.h>
#include <cstdint>
#include <cstddef>

// x = [u*m, u, m] (96) ; h = relu(x @ w1^T + b1) (8) ; out = sigmoid(h @ w2^T + b2)
// Tensor path: D[128,8] = X[128,96] @ W1^T[96,8] via mma.sync.m16n8k8 tf32
// (plain sm_80+ PTX -- no tcgen05 / arch-'a' features, which this toolchain
// rejects for sm_103).

#define NTHREADS 128
#define ELTS 128            // elements per CTA (1 per thread)
#define XSTRIDE 100         // floats per X row (96 + 4 pad; (4r+c)%32 perm -> conflict-free)

__device__ __forceinline__ float tf32r(float x) {
    uint32_t u;
    asm("cvt.rna.tf32.f32 %0, %1;" : "=r"(u) : "f"(x));
    return __uint_as_float(u);
}

__device__ __forceinline__ uint32_t tf32b(float x) {
    uint32_t u;
    asm("cvt.rna.tf32.f32 %0, %1;" : "=r"(u) : "f"(x));
    return u;
}

__device__ __forceinline__ void mma_tf32(float* c,
                                         uint32_t a0, uint32_t a1,
                                         uint32_t a2, uint32_t a3,
                                         uint32_t b0, uint32_t b1) {
    asm volatile(
        "mma.sync.aligned.m16n8k8.row.col.f32.tf32.tf32.f32 "
        "{%0,%1,%2,%3}, {%4,%5,%6,%7}, {%8,%9}, {%0,%1,%2,%3};"
        : "+f"(c[0]), "+f"(c[1]), "+f"(c[2]), "+f"(c[3])
        : "r"(a0), "r"(a1), "r"(a2), "r"(a3), "r"(b0), "r"(b1));
}

__global__ __launch_bounds__(NTHREADS, 4)
void neuralnet_mma_kernel(const int* __restrict__ users,
                          const int* __restrict__ movies,
                          const float* __restrict__ user_emb,
                          const float* __restrict__ movie_emb,
                          const float* __restrict__ w1,
                          const float* __restrict__ b1,
                          const float* __restrict__ w2,
                          const float* __restrict__ b2,
                          float* __restrict__ out,
                          int n) {
    extern __shared__ __align__(16) float Xs[];   // [128][XSTRIDE]

    const unsigned FULL = 0xffffffffu;
    const int tid = threadIdx.x;
    const int l = tid & 31;
    const int w = tid >> 5;
    const int blockBase = blockIdx.x * ELTS;

    // ---- W1 b-frags: register-resident, loaded once (L1-cached across CTAs) ----
    // m16n8k8 B layout (col-major k x n): b0 = B[k=l%4 + 8s][n=l/4], b1 = k+4.
    // B[k][n] = w1[n][k]  (w1 is [8][96] row-major).
    const int bn = l >> 2, bk = l & 3;
    uint32_t bw0[12], bw1[12];
#pragma unroll
    for (int s = 0; s < 12; ++s) {
        bw0[s] = tf32b(__ldg(&w1[bn * 96 + 8 * s + bk]));
        bw1[s] = tf32b(__ldg(&w1[bn * 96 + 8 * s + 4 + bk]));
    }
    const float b1a = __ldg(&b1[2 * bk]);       // note: epilogue col group = l&3
    const float b1b = __ldg(&b1[2 * bk + 1]);
    const float w2a = __ldg(&w2[2 * bk]);
    const float w2b = __ldg(&w2[2 * bk + 1]);
    const float bb2 = __ldg(&b2[0]);

    // ---- cooperative coalesced gather: warp w owns rows [32w, 32w+32) ----
    int eg = blockBase + (w << 5) + l;
    int ec = (eg < n) ? eg : (n - 1);
    const int uidx = users[ec];
    const int midx = movies[ec];

    const int chunk = l & 7;       // 16B chunk within 128B row
    const int esub = l >> 3;       // 0..3
    float* xbase = Xs + (w << 5) * XSTRIDE;

#pragma unroll
    for (int half = 0; half < 2; ++half) {
        float4 uu[4], mm[4];
#pragma unroll
        for (int i2 = 0; i2 < 4; ++i2) {
            const int i = half * 4 + i2;
            const int src = 4 * i + esub;      // warp-local element this lane serves
            const int ue = __shfl_sync(FULL, uidx, src);
            const int me = __shfl_sync(FULL, midx, src);
            uu[i2] = *(const float4*)(user_emb + (size_t)ue * 32 + (chunk << 2));
            mm[i2] = *(const float4*)(movie_emb + (size_t)me * 32 + (chunk << 2));
        }
#pragma unroll
        for (int i2 = 0; i2 < 4; ++i2) {
            const int i = half * 4 + i2;
            const int row = 4 * i + esub;
            float* xr = xbase + row * XSTRIDE + (chunk << 2);
            float4 u4 = uu[i2], m4 = mm[i2];
            float4 p4 = make_float4(tf32r(u4.x * m4.x), tf32r(u4.y * m4.y),
                                    tf32r(u4.z * m4.z), tf32r(u4.w * m4.w));
            u4 = make_float4(tf32r(u4.x), tf32r(u4.y), tf32r(u4.z), tf32r(u4.w));
            m4 = make_float4(tf32r(m4.x), tf32r(m4.y), tf32r(m4.z), tf32r(m4.w));
            *(float4*)(xr) = p4;         // cols 0..31  : u*m
            *(float4*)(xr + 32) = u4;    // cols 32..63 : u
            *(float4*)(xr + 64) = m4;    // cols 64..95 : m
        }
    }
    __syncwarp();

    // ---- GEMM: 2 m-tiles (16 rows each) x 12 k-steps per warp ----
    const int ar = l >> 2;      // a-frag row-in-tile
    const int ac = l & 3;       // a-frag col group
    float acc[2][4] = {{0.f, 0.f, 0.f, 0.f}, {0.f, 0.f, 0.f, 0.f}};

#pragma unroll
    for (int s = 0; s < 12; ++s) {
        const int k0 = 8 * s + ac;
#pragma unroll
        for (int t = 0; t < 2; ++t) {
            const float* rp = xbase + (t * 16 + ar) * XSTRIDE;
            uint32_t a0 = __float_as_uint(rp[k0]);
            uint32_t a1 = __float_as_uint(rp[8 * XSTRIDE + k0]);
            uint32_t a2 = __float_as_uint(rp[k0 + 4]);
            uint32_t a3 = __float_as_uint(rp[8 * XSTRIDE + k0 + 4]);
            mma_tf32(acc[t], a0, a1, a2, a3, bw0[s], bw1[s]);
        }
    }

    // ---- epilogue: relu + bias, dot with w2 across the quad, sigmoid ----
    // c-frag: rows {ar, ar+8} (+16t), cols {2*ac, 2*ac+1}
#pragma unroll
    for (int t = 0; t < 2; ++t) {
        float z0 = fmaxf(acc[t][0] + b1a, 0.f) * w2a +
                   fmaxf(acc[t][1] + b1b, 0.f) * w2b;
        float z1 = fmaxf(acc[t][2] + b1a, 0.f) * w2a +
                   fmaxf(acc[t][3] + b1b, 0.f) * w2b;
        z0 += __shfl_xor_sync(FULL, z0, 1);
        z0 += __shfl_xor_sync(FULL, z0, 2);
        z1 += __shfl_xor_sync(FULL, z1, 1);
        z1 += __shfl_xor_sync(FULL, z1, 2);
        if (ac == 0) {
            const int e0 = blockBase + (w << 5) + t * 16 + ar;
            if (e0 < n) out[e0] = 1.0f / (1.0f + __expf(-(z0 + bb2)));
            const int e1 = e0 + 8;
            if (e1 < n) out[e1] = 1.0f / (1.0f + __expf(-(z1 + bb2)));
        }
    }
}

extern "C" void kernel_launch(void* const* d_in, const int* in_sizes, int n_in,
                              void* d_out, int out_size) {
    const int*   users     = (const int*)d_in[0];
    const int*   movies    = (const int*)d_in[1];
    const float* user_emb  = (const float*)d_in[2];
    const float* movie_emb = (const float*)d_in[3];
    const float* w1        = (const float*)d_in[4];
    const float* b1        = (const float*)d_in[5];
    const float* w2        = (const float*)d_in[6];
    const float* b2        = (const float*)d_in[7];
    int n = in_sizes[0];

    const int smem = ELTS * XSTRIDE * sizeof(float);   // 51200 B
    static bool attr_set = false;
    if (!attr_set) {
        cudaFuncSetAttribute(neuralnet_mma_kernel,
                             cudaFuncAttributeMaxDynamicSharedMemorySize, smem);
        attr_set = true;
    }
    int blocks = (n + ELTS - 1) / ELTS;
    neuralnet_mma_kernel<<<blocks, NTHREADS, smem>>>(
        users, movies, user_emb, movie_emb, w1, b1, w2, b2, (float*)d_out, n);
}

// round 4
// speedup vs baseline: 1.4305x; 1.2261x over previous
#include <cuda_runtime.h>
#include <cuda_fp16.h>
#include <cstdint>
#include <cstddef>

// x = [u*m, u, m] (96) ; h = relu(x @ w1^T + b1) (8) ; out = sigmoid(h @ w2^T + b2)
// D[128,8] = X[128,96]@W1^T via mma.sync.m16n8k16 fp16 (fp32 accum).
// um scaled by 256 in X; w1 cols 0..31 scaled by 1/256 in b-frags (k-steps 0,1).

#define NTHREADS 128
#define ELTS 128
#define ROWB 208            // bytes per X row: 96 halves (192B) + 16B pad; 13*16B -> LDSM conflict-free
#define UM_SCALE 256.0f
#define UM_INV (1.0f / 256.0f)

__device__ __forceinline__ uint32_t packh2(float a, float b) {
    __half2 h = __floats2half2_rn(a, b);
    return *(uint32_t*)&h;
}

__device__ __forceinline__ void mma_f16(float* c, uint32_t a0, uint32_t a1,
                                        uint32_t a2, uint32_t a3,
                                        uint32_t b0, uint32_t b1) {
    asm volatile(
        "mma.sync.aligned.m16n8k16.row.col.f32.f16.f16.f32 "
        "{%0,%1,%2,%3}, {%4,%5,%6,%7}, {%8,%9}, {%0,%1,%2,%3};"
        : "+f"(c[0]), "+f"(c[1]), "+f"(c[2]), "+f"(c[3])
        : "r"(a0), "r"(a1), "r"(a2), "r"(a3), "r"(b0), "r"(b1));
}

__global__ __launch_bounds__(NTHREADS, 8)
void neuralnet_mma16_kernel(const int* __restrict__ users,
                            const int* __restrict__ movies,
                            const float* __restrict__ user_emb,
                            const float* __restrict__ movie_emb,
                            const float* __restrict__ w1,
                            const float* __restrict__ b1,
                            const float* __restrict__ w2,
                            const float* __restrict__ b2,
                            float* __restrict__ out,
                            int n) {
    extern __shared__ __align__(16) char Xs[];   // [128 rows][ROWB bytes]

    const unsigned FULL = 0xffffffffu;
    const int tid = threadIdx.x;
    const int l = tid & 31;
    const int w = tid >> 5;
    const int blockBase = blockIdx.x * ELTS;
    char* xwarp = Xs + (size_t)(w << 5) * ROWB;

    // ---- b-frags (registers, loaded once; L1-cached across CTAs) ----
    // m16n8k16 B (k x n col-major): lane l -> n = l>>2; b0 = {k0, k0+1}, b1 = {k0+8, k0+9},
    // k0 = 16*s + 2*(l&3).  B[k][n] = w1[n][k]; cols < 32 scaled by 1/256.
    const int bn = l >> 2, bk = l & 3;
    uint32_t B0[6], B1[6];
#pragma unroll
    for (int s = 0; s < 6; ++s) {
        const int k0 = 16 * s + 2 * bk;
        const float sc = (s < 2) ? UM_INV : 1.0f;
        const float* wr = w1 + bn * 96 + k0;
        B0[s] = packh2(__ldg(wr) * sc, __ldg(wr + 1) * sc);
        B1[s] = packh2(__ldg(wr + 8) * sc, __ldg(wr + 9) * sc);
    }
    const float b1a = __ldg(&b1[2 * bk]);
    const float b1b = __ldg(&b1[2 * bk + 1]);
    const float w2a = __ldg(&w2[2 * bk]);
    const float w2b = __ldg(&w2[2 * bk + 1]);
    const float bb2 = __ldg(&b2[0]);

    // ---- cooperative coalesced gather: warp owns elements [32w, 32w+32) ----
    int eg = blockBase + (w << 5) + l;
    int ec = (eg < n) ? eg : (n - 1);
    const int uidx = users[ec];
    const int midx = movies[ec];

    const int chunk = l & 7;     // 16B chunk of the 128B embedding row
    const int esub = l >> 3;     // 0..3

#pragma unroll
    for (int i = 0; i < 8; ++i) {
        const int src = 4 * i + esub;            // warp-local element served
        const int ue = __shfl_sync(FULL, uidx, src);
        const int me = __shfl_sync(FULL, midx, src);
        const float4 u4 = *(const float4*)(user_emb + (size_t)ue * 32 + (chunk << 2));
        const float4 m4 = *(const float4*)(movie_emb + (size_t)me * 32 + (chunk << 2));

        char* xr = xwarp + (size_t)src * ROWB + (chunk << 3);
        uint2 um = make_uint2(packh2(u4.x * m4.x * UM_SCALE, u4.y * m4.y * UM_SCALE),
                              packh2(u4.z * m4.z * UM_SCALE, u4.w * m4.w * UM_SCALE));
        uint2 uu = make_uint2(packh2(u4.x, u4.y), packh2(u4.z, u4.w));
        uint2 mm = make_uint2(packh2(m4.x, m4.y), packh2(m4.z, m4.w));
        *(uint2*)(xr)       = um;    // cols 0..31  (bytes 0..63)
        *(uint2*)(xr + 64)  = uu;    // cols 32..63
        *(uint2*)(xr + 128) = mm;    // cols 64..95
    }
    __syncwarp();

    // ---- GEMM: 2 m-tiles x 6 k-steps, a-frags via ldmatrix.x4 ----
    const uint32_t xs = (uint32_t)__cvta_generic_to_shared(xwarp);
    float acc[2][4] = {{0.f, 0.f, 0.f, 0.f}, {0.f, 0.f, 0.f, 0.f}};

#pragma unroll
    for (int s = 0; s < 6; ++s) {
#pragma unroll
        for (int t = 0; t < 2; ++t) {
            const uint32_t addr = xs + (uint32_t)((t * 16 + (l & 15)) * ROWB)
                                + (uint32_t)(s * 32) + (uint32_t)((l >> 4) << 4);
            uint32_t a0, a1, a2, a3;
            asm volatile("ldmatrix.sync.aligned.m8n8.x4.shared.b16 {%0,%1,%2,%3}, [%4];"
                         : "=r"(a0), "=r"(a1), "=r"(a2), "=r"(a3) : "r"(addr));
            mma_f16(acc[t], a0, a1, a2, a3, B0[s], B1[s]);
        }
    }

    // ---- epilogue: relu+bias, dot w2 across quad, sigmoid ----
    // c-frag rows {l>>2, l>>2+8} (+16t), cols {2*bk, 2*bk+1}
#pragma unroll
    for (int t = 0; t < 2; ++t) {
        float z0 = fmaxf(acc[t][0] + b1a, 0.f) * w2a +
                   fmaxf(acc[t][1] + b1b, 0.f) * w2b;
        float z1 = fmaxf(acc[t][2] + b1a, 0.f) * w2a +
                   fmaxf(acc[t][3] + b1b, 0.f) * w2b;
        z0 += __shfl_xor_sync(FULL, z0, 1);
        z0 += __shfl_xor_sync(FULL, z0, 2);
        z1 += __shfl_xor_sync(FULL, z1, 1);
        z1 += __shfl_xor_sync(FULL, z1, 2);
        if (bk == 0) {
            const int e0 = blockBase + (w << 5) + t * 16 + (l >> 2);
            if (e0 < n) out[e0] = 1.0f / (1.0f + __expf(-(z0 + bb2)));
            const int e1 = e0 + 8;
            if (e1 < n) out[e1] = 1.0f / (1.0f + __expf(-(z1 + bb2)));
        }
    }
}

extern "C" void kernel_launch(void* const* d_in, const int* in_sizes, int n_in,
                              void* d_out, int out_size) {
    const int*   users     = (const int*)d_in[0];
    const int*   movies    = (const int*)d_in[1];
    const float* user_emb  = (const float*)d_in[2];
    const float* movie_emb = (const float*)d_in[3];
    const float* w1        = (const float*)d_in[4];
    const float* b1        = (const float*)d_in[5];
    const float* w2        = (const float*)d_in[6];
    const float* b2        = (const float*)d_in[7];
    int n = in_sizes[0];

    const int smem = ELTS * ROWB;     // 26624 B -> 8 CTAs/SM
    int blocks = (n + ELTS - 1) / ELTS;
    neuralnet_mma16_kernel<<<blocks, NTHREADS, smem>>>(
        users, movies, user_emb, movie_emb, w1, b1, w2, b2, (float*)d_out, n);
}

// round 5
// speedup vs baseline: 1.7630x; 1.2324x over previous
#include <cuda_runtime.h>
#include <cuda_fp16.h>
#include <cstdint>
#include <cstddef>

// x = [u*m, u, m] (96) ; h = relu(x @ w1^T + b1) (8) ; out = sigmoid(h @ w2^T + b2)
// D[128,8] = X@W1^T via mma.sync.m16n8k16 fp16 (fp32 accum).
// SMEM holds only [64*u | m] (128B/row). um a-frags = hmul2(u_frag, m_frag) in
// registers (regions have identical ldmatrix geometry -> frags align elementwise).
// b-frags: k-steps 0..3 (wA, wB) scaled by 1/64 to cancel the 64*u scaling.

#define NTHREADS 128
#define ELTS 128
#define ROWB 144            // 64B u + 64B m + 16B pad; 144 mod 128 = 16 -> ldmatrix conflict-free
#define U_SCALE 64.0f
#define U_INV (1.0f / 64.0f)

__device__ __forceinline__ uint32_t packh2(float a, float b) {
    __half2 h = __floats2half2_rn(a, b);
    return *(uint32_t*)&h;
}

__device__ __forceinline__ uint32_t hmul2u(uint32_t a, uint32_t b) {
    __half2 r = __hmul2(*(__half2*)&a, *(__half2*)&b);
    return *(uint32_t*)&r;
}

__device__ __forceinline__ void mma_f16(float* c, uint32_t a0, uint32_t a1,
                                        uint32_t a2, uint32_t a3,
                                        uint32_t b0, uint32_t b1) {
    asm volatile(
        "mma.sync.aligned.m16n8k16.row.col.f32.f16.f16.f32 "
        "{%0,%1,%2,%3}, {%4,%5,%6,%7}, {%8,%9}, {%0,%1,%2,%3};"
        : "+f"(c[0]), "+f"(c[1]), "+f"(c[2]), "+f"(c[3])
        : "r"(a0), "r"(a1), "r"(a2), "r"(a3), "r"(b0), "r"(b1));
}

__device__ __forceinline__ void ldsm4(uint32_t* r, uint32_t addr) {
    asm volatile("ldmatrix.sync.aligned.m8n8.x4.shared.b16 {%0,%1,%2,%3}, [%4];"
                 : "=r"(r[0]), "=r"(r[1]), "=r"(r[2]), "=r"(r[3]) : "r"(addr));
}

__global__ __launch_bounds__(NTHREADS, 8)
void neuralnet_mma16b_kernel(const int* __restrict__ users,
                             const int* __restrict__ movies,
                             const float* __restrict__ user_emb,
                             const float* __restrict__ movie_emb,
                             const float* __restrict__ w1,
                             const float* __restrict__ b1,
                             const float* __restrict__ w2,
                             const float* __restrict__ b2,
                             float* __restrict__ out,
                             int n) {
    extern __shared__ __align__(16) char Xs[];   // [128 rows][ROWB bytes]

    const unsigned FULL = 0xffffffffu;
    const int tid = threadIdx.x;
    const int l = tid & 31;
    const int w = tid >> 5;
    const int blockBase = blockIdx.x * ELTS;
    char* xwarp = Xs + (size_t)(w << 5) * ROWB;

    // ---- b-frags (registers, once per thread; L1-cached across CTAs) ----
    // m16n8k16 B: lane l -> n = l>>2; b0 = {k0,k0+1}, b1 = {k0+8,k0+9}, k0 = 16s+2(l&3).
    // Logical k-order: s0,s1 = um (w1 cols 0..31, scale 1/64 cancels 64u),
    //                  s2,s3 = u  (w1 cols 32..63, scale 1/64),
    //                  s4,s5 = m  (w1 cols 64..95, scale 1).
    const int bn = l >> 2, bk = l & 3;
    uint32_t B0[6], B1[6];
#pragma unroll
    for (int s = 0; s < 6; ++s) {
        const int k0 = 16 * s + 2 * bk;
        const float sc = (s < 4) ? U_INV : 1.0f;
        const float* wr = w1 + bn * 96 + k0;
        B0[s] = packh2(__ldg(wr) * sc, __ldg(wr + 1) * sc);
        B1[s] = packh2(__ldg(wr + 8) * sc, __ldg(wr + 9) * sc);
    }
    const float b1a = __ldg(&b1[2 * bk]);
    const float b1b = __ldg(&b1[2 * bk + 1]);
    const float w2a = __ldg(&w2[2 * bk]);
    const float w2b = __ldg(&w2[2 * bk + 1]);
    const float bb2 = __ldg(&b2[0]);

    // ---- cooperative coalesced gather: warp owns elements [32w, 32w+32) ----
    int eg = blockBase + (w << 5) + l;
    int ec = (eg < n) ? eg : (n - 1);
    const int uidx = users[ec];
    const int midx = movies[ec];

    const int chunk = l & 7;     // 16B chunk of the 128B embedding row
    const int esub = l >> 3;     // 0..3

#pragma unroll
    for (int i = 0; i < 8; ++i) {
        const int src = 4 * i + esub;            // warp-local element served
        const int ue = __shfl_sync(FULL, uidx, src);
        const int me = __shfl_sync(FULL, midx, src);
        const float4 u4 = *(const float4*)(user_emb + (size_t)ue * 32 + (chunk << 2));
        const float4 m4 = *(const float4*)(movie_emb + (size_t)me * 32 + (chunk << 2));

        char* xr = xwarp + (size_t)src * ROWB + (chunk << 3);
        *(uint2*)(xr) = make_uint2(packh2(u4.x * U_SCALE, u4.y * U_SCALE),
                                   packh2(u4.z * U_SCALE, u4.w * U_SCALE));
        *(uint2*)(xr + 64) = make_uint2(packh2(m4.x, m4.y), packh2(m4.z, m4.w));
    }
    __syncwarp();

    // ---- GEMM: 2 m-tiles; u,m frags via ldmatrix, um frags via hmul2 ----
    const uint32_t xs = (uint32_t)__cvta_generic_to_shared(xwarp);
    float acc[2][4] = {{0.f, 0.f, 0.f, 0.f}, {0.f, 0.f, 0.f, 0.f}};

#pragma unroll
    for (int t = 0; t < 2; ++t) {
        const uint32_t abase = xs + (uint32_t)((t * 16 + (l & 15)) * ROWB)
                             + (uint32_t)((l >> 4) << 4);
        uint32_t U[2][4], M[2][4];
        ldsm4(U[0], abase);
        ldsm4(U[1], abase + 32);
        ldsm4(M[0], abase + 64);
        ldsm4(M[1], abase + 96);

        uint32_t P[4];
#pragma unroll
        for (int j = 0; j < 4; ++j) P[j] = hmul2u(U[0][j], M[0][j]);
        mma_f16(acc[t], P[0], P[1], P[2], P[3], B0[0], B1[0]);
#pragma unroll
        for (int j = 0; j < 4; ++j) P[j] = hmul2u(U[1][j], M[1][j]);
        mma_f16(acc[t], P[0], P[1], P[2], P[3], B0[1], B1[1]);

        mma_f16(acc[t], U[0][0], U[0][1], U[0][2], U[0][3], B0[2], B1[2]);
        mma_f16(acc[t], U[1][0], U[1][1], U[1][2], U[1][3], B0[3], B1[3]);
        mma_f16(acc[t], M[0][0], M[0][1], M[0][2], M[0][3], B0[4], B1[4]);
        mma_f16(acc[t], M[1][0], M[1][1], M[1][2], M[1][3], B0[5], B1[5]);
    }

    // ---- epilogue: relu+bias, dot w2 across quad, sigmoid ----
    // c-frag rows {l>>2, l>>2+8} (+16t), cols {2*bk, 2*bk+1}
#pragma unroll
    for (int t = 0; t < 2; ++t) {
        float z0 = fmaxf(acc[t][0] + b1a, 0.f) * w2a +
                   fmaxf(acc[t][1] + b1b, 0.f) * w2b;
        float z1 = fmaxf(acc[t][2] + b1a, 0.f) * w2a +
                   fmaxf(acc[t][3] + b1b, 0.f) * w2b;
        z0 += __shfl_xor_sync(FULL, z0, 1);
        z0 += __shfl_xor_sync(FULL, z0, 2);
        z1 += __shfl_xor_sync(FULL, z1, 1);
        z1 += __shfl_xor_sync(FULL, z1, 2);
        if (bk == 0) {
            const int e0 = blockBase + (w << 5) + t * 16 + (l >> 2);
            if (e0 < n) out[e0] = 1.0f / (1.0f + __expf(-(z0 + bb2)));
            const int e1 = e0 + 8;
            if (e1 < n) out[e1] = 1.0f / (1.0f + __expf(-(z1 + bb2)));
        }
    }
}

extern "C" void kernel_launch(void* const* d_in, const int* in_sizes, int n_in,
                              void* d_out, int out_size) {
    const int*   users     = (const int*)d_in[0];
    const int*   movies    = (const int*)d_in[1];
    const float* user_emb  = (const float*)d_in[2];
    const float* movie_emb = (const float*)d_in[3];
    const float* w1        = (const float*)d_in[4];
    const float* b1        = (const float*)d_in[5];
    const float* w2        = (const float*)d_in[6];
    const float* b2        = (const float*)d_in[7];
    int n = in_sizes[0];

    const int smem = ELTS * ROWB;     // 18432 B
    int blocks = (n + ELTS - 1) / ELTS;
    neuralnet_mma16b_kernel<<<blocks, NTHREADS, smem>>>(
        users, movies, user_emb, movie_emb, w1, b1, w2, b2, (float*)d_out, n);
}

// round 6
// speedup vs baseline: 1.7711x; 1.0046x over previous
#include <cuda_runtime.h>
#include <cuda_fp16.h>
#include <cstdint>
#include <cstddef>

// x = [u*m, u, m] (96) ; h = relu(x @ w1^T + b1) (8) ; out = sigmoid(h @ w2^T + b2)
// D[128,8] = X@W1^T via mma.sync.m16n8k16 fp16 (fp32 accum).
// SMEM holds only [64*u | m] (128B/row); um a-frags = hmul2(u_frag, m_frag).
// b-frags k-steps 0..3 scaled by 1/64 to cancel the 64u scaling.
// R6: gather loads use ld.global.L1::no_allocate (streaming; no L1 line
// allocation/eviction work on the ~always-miss embedding gathers).

#define NTHREADS 128
#define ELTS 128
#define ROWB 144            // 64B u + 64B m + 16B pad
#define U_SCALE 64.0f
#define U_INV (1.0f / 64.0f)

__device__ __forceinline__ float4 ldg_na128(const float* p) {
    float4 v;
    asm volatile("ld.global.L1::no_allocate.v4.f32 {%0,%1,%2,%3}, [%4];"
                 : "=f"(v.x), "=f"(v.y), "=f"(v.z), "=f"(v.w) : "l"(p));
    return v;
}

__device__ __forceinline__ uint32_t packh2(float a, float b) {
    __half2 h = __floats2half2_rn(a, b);
    return *(uint32_t*)&h;
}

__device__ __forceinline__ uint32_t hmul2u(uint32_t a, uint32_t b) {
    __half2 r = __hmul2(*(__half2*)&a, *(__half2*)&b);
    return *(uint32_t*)&r;
}

__device__ __forceinline__ void mma_f16(float* c, uint32_t a0, uint32_t a1,
                                        uint32_t a2, uint32_t a3,
                                        uint32_t b0, uint32_t b1) {
    asm volatile(
        "mma.sync.aligned.m16n8k16.row.col.f32.f16.f16.f32 "
        "{%0,%1,%2,%3}, {%4,%5,%6,%7}, {%8,%9}, {%0,%1,%2,%3};"
        : "+f"(c[0]), "+f"(c[1]), "+f"(c[2]), "+f"(c[3])
        : "r"(a0), "r"(a1), "r"(a2), "r"(a3), "r"(b0), "r"(b1));
}

__device__ __forceinline__ void ldsm4(uint32_t* r, uint32_t addr) {
    asm volatile("ldmatrix.sync.aligned.m8n8.x4.shared.b16 {%0,%1,%2,%3}, [%4];"
                 : "=r"(r[0]), "=r"(r[1]), "=r"(r[2]), "=r"(r[3]) : "r"(addr));
}

__global__ __launch_bounds__(NTHREADS, 8)
void neuralnet_mma16c_kernel(const int* __restrict__ users,
                             const int* __restrict__ movies,
                             const float* __restrict__ user_emb,
                             const float* __restrict__ movie_emb,
                             const float* __restrict__ w1,
                             const float* __restrict__ b1,
                             const float* __restrict__ w2,
                             const float* __restrict__ b2,
                             float* __restrict__ out,
                             int n) {
    extern __shared__ __align__(16) char Xs[];   // [128 rows][ROWB bytes]

    const unsigned FULL = 0xffffffffu;
    const int tid = threadIdx.x;
    const int l = tid & 31;
    const int w = tid >> 5;
    const int blockBase = blockIdx.x * ELTS;
    char* xwarp = Xs + (size_t)(w << 5) * ROWB;

    // ---- b-frags (registers, once per thread; L1-cached across CTAs) ----
    const int bn = l >> 2, bk = l & 3;
    uint32_t B0[6], B1[6];
#pragma unroll
    for (int s = 0; s < 6; ++s) {
        const int k0 = 16 * s + 2 * bk;
        const float sc = (s < 4) ? U_INV : 1.0f;
        const float* wr = w1 + bn * 96 + k0;
        B0[s] = packh2(__ldg(wr) * sc, __ldg(wr + 1) * sc);
        B1[s] = packh2(__ldg(wr + 8) * sc, __ldg(wr + 9) * sc);
    }
    const float b1a = __ldg(&b1[2 * bk]);
    const float b1b = __ldg(&b1[2 * bk + 1]);
    const float w2a = __ldg(&w2[2 * bk]);
    const float w2b = __ldg(&w2[2 * bk + 1]);
    const float bb2 = __ldg(&b2[0]);

    // ---- cooperative coalesced gather (streaming loads, no L1 allocate) ----
    int eg = blockBase + (w << 5) + l;
    int ec = (eg < n) ? eg : (n - 1);
    const int uidx = users[ec];
    const int midx = movies[ec];

    const int chunk = l & 7;     // 16B chunk of the 128B embedding row
    const int esub = l >> 3;     // 0..3

#pragma unroll
    for (int i = 0; i < 8; ++i) {
        const int src = 4 * i + esub;            // warp-local element served
        const int ue = __shfl_sync(FULL, uidx, src);
        const int me = __shfl_sync(FULL, midx, src);
        const float4 u4 = ldg_na128(user_emb + (size_t)ue * 32 + (chunk << 2));
        const float4 m4 = ldg_na128(movie_emb + (size_t)me * 32 + (chunk << 2));

        char* xr = xwarp + (size_t)src * ROWB + (chunk << 3);
        *(uint2*)(xr) = make_uint2(packh2(u4.x * U_SCALE, u4.y * U_SCALE),
                                   packh2(u4.z * U_SCALE, u4.w * U_SCALE));
        *(uint2*)(xr + 64) = make_uint2(packh2(m4.x, m4.y), packh2(m4.z, m4.w));
    }
    __syncwarp();

    // ---- GEMM: 2 m-tiles; u,m frags via ldmatrix, um frags via hmul2 ----
    const uint32_t xs = (uint32_t)__cvta_generic_to_shared(xwarp);
    float acc[2][4] = {{0.f, 0.f, 0.f, 0.f}, {0.f, 0.f, 0.f, 0.f}};

#pragma unroll
    for (int t = 0; t < 2; ++t) {
        const uint32_t abase = xs + (uint32_t)((t * 16 + (l & 15)) * ROWB)
                             + (uint32_t)((l >> 4) << 4);
        uint32_t U[2][4], M[2][4];
        ldsm4(U[0], abase);
        ldsm4(U[1], abase + 32);
        ldsm4(M[0], abase + 64);
        ldsm4(M[1], abase + 96);

        uint32_t P[4];
#pragma unroll
        for (int j = 0; j < 4; ++j) P[j] = hmul2u(U[0][j], M[0][j]);
        mma_f16(acc[t], P[0], P[1], P[2], P[3], B0[0], B1[0]);
#pragma unroll
        for (int j = 0; j < 4; ++j) P[j] = hmul2u(U[1][j], M[1][j]);
        mma_f16(acc[t], P[0], P[1], P[2], P[3], B0[1], B1[1]);

        mma_f16(acc[t], U[0][0], U[0][1], U[0][2], U[0][3], B0[2], B1[2]);
        mma_f16(acc[t], U[1][0], U[1][1], U[1][2], U[1][3], B0[3], B1[3]);
        mma_f16(acc[t], M[0][0], M[0][1], M[0][2], M[0][3], B0[4], B1[4]);
        mma_f16(acc[t], M[1][0], M[1][1], M[1][2], M[1][3], B0[5], B1[5]);
    }

    // ---- epilogue: relu+bias, dot w2 across quad, sigmoid ----
#pragma unroll
    for (int t = 0; t < 2; ++t) {
        float z0 = fmaxf(acc[t][0] + b1a, 0.f) * w2a +
                   fmaxf(acc[t][1] + b1b, 0.f) * w2b;
        float z1 = fmaxf(acc[t][2] + b1a, 0.f) * w2a +
                   fmaxf(acc[t][3] + b1b, 0.f) * w2b;
        z0 += __shfl_xor_sync(FULL, z0, 1);
        z0 += __shfl_xor_sync(FULL, z0, 2);
        z1 += __shfl_xor_sync(FULL, z1, 1);
        z1 += __shfl_xor_sync(FULL, z1, 2);
        if (bk == 0) {
            const int e0 = blockBase + (w << 5) + t * 16 + (l >> 2);
            if (e0 < n) out[e0] = 1.0f / (1.0f + __expf(-(z0 + bb2)));
            const int e1 = e0 + 8;
            if (e1 < n) out[e1] = 1.0f / (1.0f + __expf(-(z1 + bb2)));
        }
    }
}

extern "C" void kernel_launch(void* const* d_in, const int* in_sizes, int n_in,
                              void* d_out, int out_size) {
    const int*   users     = (const int*)d_in[0];
    const int*   movies    = (const int*)d_in[1];
    const float* user_emb  = (const float*)d_in[2];
    const float* movie_emb = (const float*)d_in[3];
    const float* w1        = (const float*)d_in[4];
    const float* b1        = (const float*)d_in[5];
    const float* w2        = (const float*)d_in[6];
    const float* b2        = (const float*)d_in[7];
    int n = in_sizes[0];

    const int smem = ELTS * ROWB;     // 18432 B
    int blocks = (n + ELTS - 1) / ELTS;
    neuralnet_mma16c_kernel<<<blocks, NTHREADS, smem>>>(
        users, movies, user_emb, movie_emb, w1, b1, w2, b2, (float*)d_out, n);
}

// round 7
// speedup vs baseline: 1.8375x; 1.0375x over previous
#include <cuda_runtime.h>
#include <cuda_fp16.h>
#include <cstdint>
#include <cstddef>

// x = [u*m, u, m] (96) ; h = relu(x @ w1^T + b1) (8) ; out = sigmoid(h @ w2^T + b2)
// D[128,8] = X@W1^T via mma.sync.m16n8k16 fp16 (fp32 accum).
// SMEM holds only [64*u | m] (128B/row); um a-frags = hmul2(u_frag, m_frag).
// b-frags k-steps 0..3 scaled by 1/64 to cancel the 64u scaling.
// R7: __launch_bounds__(128,10) -> 48 regs -> 10 CTAs/SM (occ 45%->62%) to
// keep the saturated L1tex pipe fed; 2-deep pipelined gather for MLP.

#define NTHREADS 128
#define ELTS 128
#define ROWB 144            // 64B u + 64B m + 16B pad
#define U_SCALE 64.0f
#define U_INV (1.0f / 64.0f)

__device__ __forceinline__ float4 ldg_na128(const float* p) {
    float4 v;
    asm volatile("ld.global.L1::no_allocate.v4.f32 {%0,%1,%2,%3}, [%4];"
                 : "=f"(v.x), "=f"(v.y), "=f"(v.z), "=f"(v.w) : "l"(p));
    return v;
}

__device__ __forceinline__ uint32_t packh2(float a, float b) {
    __half2 h = __floats2half2_rn(a, b);
    return *(uint32_t*)&h;
}

__device__ __forceinline__ uint32_t hmul2u(uint32_t a, uint32_t b) {
    __half2 r = __hmul2(*(__half2*)&a, *(__half2*)&b);
    return *(uint32_t*)&r;
}

__device__ __forceinline__ void mma_f16(float* c, uint32_t a0, uint32_t a1,
                                        uint32_t a2, uint32_t a3,
                                        uint32_t b0, uint32_t b1) {
    asm volatile(
        "mma.sync.aligned.m16n8k16.row.col.f32.f16.f16.f32 "
        "{%0,%1,%2,%3}, {%4,%5,%6,%7}, {%8,%9}, {%0,%1,%2,%3};"
        : "+f"(c[0]), "+f"(c[1]), "+f"(c[2]), "+f"(c[3])
        : "r"(a0), "r"(a1), "r"(a2), "r"(a3), "r"(b0), "r"(b1));
}

__device__ __forceinline__ void ldsm4(uint32_t* r, uint32_t addr) {
    asm volatile("ldmatrix.sync.aligned.m8n8.x4.shared.b16 {%0,%1,%2,%3}, [%4];"
                 : "=r"(r[0]), "=r"(r[1]), "=r"(r[2]), "=r"(r[3]) : "r"(addr));
}

__global__ __launch_bounds__(NTHREADS, 10)
void neuralnet_mma16d_kernel(const int* __restrict__ users,
                             const int* __restrict__ movies,
                             const float* __restrict__ user_emb,
                             const float* __restrict__ movie_emb,
                             const float* __restrict__ w1,
                             const float* __restrict__ b1,
                             const float* __restrict__ w2,
                             const float* __restrict__ b2,
                             float* __restrict__ out,
                             int n) {
    extern __shared__ __align__(16) char Xs[];   // [128 rows][ROWB bytes]

    const unsigned FULL = 0xffffffffu;
    const int tid = threadIdx.x;
    const int l = tid & 31;
    const int w = tid >> 5;
    const int blockBase = blockIdx.x * ELTS;
    char* xwarp = Xs + (size_t)(w << 5) * ROWB;

    // ---- cooperative coalesced gather, 2-deep pipelined ----
    int eg = blockBase + (w << 5) + l;
    int ec = (eg < n) ? eg : (n - 1);
    const int uidx = users[ec];
    const int midx = movies[ec];

    const int chunk = l & 7;     // 16B chunk of the 128B embedding row
    const int esub = l >> 3;     // 0..3

    {
        float4 u4a, m4a;
        {
            const int ue = __shfl_sync(FULL, uidx, esub);
            const int me = __shfl_sync(FULL, midx, esub);
            u4a = ldg_na128(user_emb + (size_t)ue * 32 + (chunk << 2));
            m4a = ldg_na128(movie_emb + (size_t)me * 32 + (chunk << 2));
        }
#pragma unroll
        for (int i = 0; i < 8; ++i) {
            float4 u4 = u4a, m4 = m4a;
            if (i < 7) {
                const int src = 4 * (i + 1) + esub;
                const int ue = __shfl_sync(FULL, uidx, src);
                const int me = __shfl_sync(FULL, midx, src);
                u4a = ldg_na128(user_emb + (size_t)ue * 32 + (chunk << 2));
                m4a = ldg_na128(movie_emb + (size_t)me * 32 + (chunk << 2));
            }
            char* xr = xwarp + (size_t)(4 * i + esub) * ROWB + (chunk << 3);
            *(uint2*)(xr) = make_uint2(packh2(u4.x * U_SCALE, u4.y * U_SCALE),
                                       packh2(u4.z * U_SCALE, u4.w * U_SCALE));
            *(uint2*)(xr + 64) = make_uint2(packh2(m4.x, m4.y), packh2(m4.z, m4.w));
        }
    }

    // ---- b-frags (after gather issues, to keep gather MLP high) ----
    // m16n8k16 B: lane l -> n = l>>2; b0 = {k0,k0+1}, b1 = {k0+8,k0+9}, k0 = 16s+2(l&3).
    // s0,s1 = um (w1 cols 0..31, *1/64), s2,s3 = u (cols 32..63, *1/64), s4,s5 = m.
    const int bn = l >> 2, bk = l & 3;
    uint32_t B0[6], B1[6];
#pragma unroll
    for (int s = 0; s < 6; ++s) {
        const int k0 = 16 * s + 2 * bk;
        const float sc = (s < 4) ? U_INV : 1.0f;
        const float* wr = w1 + bn * 96 + k0;
        B0[s] = packh2(__ldg(wr) * sc, __ldg(wr + 1) * sc);
        B1[s] = packh2(__ldg(wr + 8) * sc, __ldg(wr + 9) * sc);
    }
    __syncwarp();

    // ---- GEMM: 2 m-tiles; u,m frags via ldmatrix, um frags via hmul2 ----
    const uint32_t xs = (uint32_t)__cvta_generic_to_shared(xwarp);
    float acc[2][4] = {{0.f, 0.f, 0.f, 0.f}, {0.f, 0.f, 0.f, 0.f}};

#pragma unroll
    for (int t = 0; t < 2; ++t) {
        const uint32_t abase = xs + (uint32_t)((t * 16 + (l & 15)) * ROWB)
                             + (uint32_t)((l >> 4) << 4);
        uint32_t U[2][4], M[2][4];
        ldsm4(U[0], abase);
        ldsm4(U[1], abase + 32);
        ldsm4(M[0], abase + 64);
        ldsm4(M[1], abase + 96);

        uint32_t P[4];
#pragma unroll
        for (int j = 0; j < 4; ++j) P[j] = hmul2u(U[0][j], M[0][j]);
        mma_f16(acc[t], P[0], P[1], P[2], P[3], B0[0], B1[0]);
#pragma unroll
        for (int j = 0; j < 4; ++j) P[j] = hmul2u(U[1][j], M[1][j]);
        mma_f16(acc[t], P[0], P[1], P[2], P[3], B0[1], B1[1]);

        mma_f16(acc[t], U[0][0], U[0][1], U[0][2], U[0][3], B0[2], B1[2]);
        mma_f16(acc[t], U[1][0], U[1][1], U[1][2], U[1][3], B0[3], B1[3]);
        mma_f16(acc[t], M[0][0], M[0][1], M[0][2], M[0][3], B0[4], B1[4]);
        mma_f16(acc[t], M[1][0], M[1][1], M[1][2], M[1][3], B0[5], B1[5]);
    }

    // ---- epilogue: relu+bias, dot w2 across quad, sigmoid ----
    const float b1a = __ldg(&b1[2 * bk]);
    const float b1b = __ldg(&b1[2 * bk + 1]);
    const float w2a = __ldg(&w2[2 * bk]);
    const float w2b = __ldg(&w2[2 * bk + 1]);
    const float bb2 = __ldg(&b2[0]);

#pragma unroll
    for (int t = 0; t < 2; ++t) {
        float z0 = fmaxf(acc[t][0] + b1a, 0.f) * w2a +
                   fmaxf(acc[t][1] + b1b, 0.f) * w2b;
        float z1 = fmaxf(acc[t][2] + b1a, 0.f) * w2a +
                   fmaxf(acc[t][3] + b1b, 0.f) * w2b;
        z0 += __shfl_xor_sync(FULL, z0, 1);
        z0 += __shfl_xor_sync(FULL, z0, 2);
        z1 += __shfl_xor_sync(FULL, z1, 1);
        z1 += __shfl_xor_sync(FULL, z1, 2);
        if (bk == 0) {
            const int e0 = blockBase + (w << 5) + t * 16 + (l >> 2);
            if (e0 < n) out[e0] = 1.0f / (1.0f + __expf(-(z0 + bb2)));
            const int e1 = e0 + 8;
            if (e1 < n) out[e1] = 1.0f / (1.0f + __expf(-(z1 + bb2)));
        }
    }
}

extern "C" void kernel_launch(void* const* d_in, const int* in_sizes, int n_in,
                              void* d_out, int out_size) {
    const int*   users     = (const int*)d_in[0];
    const int*   movies    = (const int*)d_in[1];
    const float* user_emb  = (const float*)d_in[2];
    const float* movie_emb = (const float*)d_in[3];
    const float* w1        = (const float*)d_in[4];
    const float* b1        = (const float*)d_in[5];
    const float* w2        = (const float*)d_in[6];
    const float* b2        = (const float*)d_in[7];
    int n = in_sizes[0];

    const int smem = ELTS * ROWB;     // 18432 B
    int blocks = (n + ELTS - 1) / ELTS;
    neuralnet_mma16d_kernel<<<blocks, NTHREADS, smem>>>(
        users, movies, user_emb, movie_emb, w1, b1, w2, b2, (float*)d_out, n);
}

// round 8
// speedup vs baseline: 2.0957x; 1.1405x over previous
#include <cuda_runtime.h>
#include <cuda_fp16.h>
#include <cstdint>
#include <cstddef>

// x = [u*m, u, m] (96) ; h = relu(x @ w1^T + b1) (8) ; out = sigmoid(h @ w2^T + b2)
// D[128,8] = X@W1^T via mma.sync.m16n8k16 fp16 (fp32 accum).
// SMEM holds [64*u | m] (128B/row); um a-frags = hmul2(u_frag, m_frag); b-frag
// k-steps 0..3 carry 1/64 to cancel the 64u scaling.
// R8: b-frags built ONCE per CTA into an SMEM table (the per-warp scattered
// w1 LDGs were ~190 l1tex wavefronts/warp -- bigger than the gather itself).
// Each thread now reads its 12 frag u32s with 3 conflict-free LDS.128.

#define NTHREADS 128
#define ELTS 128
#define ROWB 144            // 64B u + 64B m + 16B pad
#define U_SCALE 64.0f
#define U_INV (1.0f / 64.0f)

#define XS_BYTES (ELTS * ROWB)        // 18432
#define FRAG_OFF XS_BYTES             // uint32_t[384]: [lane][12] = [B0[0..5], B1[0..5]]
#define BIAS_OFF (FRAG_OFF + 1536)    // float[17]: b1[0..7], w2[8..15], b2[16]
#define SMEM_TOTAL (BIAS_OFF + 128)   // 20096 -> 10 CTAs/SM

__device__ __forceinline__ float4 ldg_na128(const float* p) {
    float4 v;
    asm volatile("ld.global.L1::no_allocate.v4.f32 {%0,%1,%2,%3}, [%4];"
                 : "=f"(v.x), "=f"(v.y), "=f"(v.z), "=f"(v.w) : "l"(p));
    return v;
}

__device__ __forceinline__ uint32_t packh2(float a, float b) {
    __half2 h = __floats2half2_rn(a, b);
    return *(uint32_t*)&h;
}

__device__ __forceinline__ uint32_t hmul2u(uint32_t a, uint32_t b) {
    __half2 r = __hmul2(*(__half2*)&a, *(__half2*)&b);
    return *(uint32_t*)&r;
}

__device__ __forceinline__ void mma_f16(float* c, uint32_t a0, uint32_t a1,
                                        uint32_t a2, uint32_t a3,
                                        uint32_t b0, uint32_t b1) {
    asm volatile(
        "mma.sync.aligned.m16n8k16.row.col.f32.f16.f16.f32 "
        "{%0,%1,%2,%3}, {%4,%5,%6,%7}, {%8,%9}, {%0,%1,%2,%3};"
        : "+f"(c[0]), "+f"(c[1]), "+f"(c[2]), "+f"(c[3])
        : "r"(a0), "r"(a1), "r"(a2), "r"(a3), "r"(b0), "r"(b1));
}

__device__ __forceinline__ void ldsm4(uint32_t* r, uint32_t addr) {
    asm volatile("ldmatrix.sync.aligned.m8n8.x4.shared.b16 {%0,%1,%2,%3}, [%4];"
                 : "=r"(r[0]), "=r"(r[1]), "=r"(r[2]), "=r"(r[3]) : "r"(addr));
}

__global__ __launch_bounds__(NTHREADS, 10)
void neuralnet_mma16e_kernel(const int* __restrict__ users,
                             const int* __restrict__ movies,
                             const float* __restrict__ user_emb,
                             const float* __restrict__ movie_emb,
                             const float* __restrict__ w1,
                             const float* __restrict__ b1,
                             const float* __restrict__ w2,
                             const float* __restrict__ b2,
                             float* __restrict__ out,
                             int n) {
    extern __shared__ __align__(16) char Xs[];
    uint32_t* fragS = (uint32_t*)(Xs + FRAG_OFF);
    float* biasS = (float*)(Xs + BIAS_OFF);

    const unsigned FULL = 0xffffffffu;
    const int tid = threadIdx.x;
    const int l = tid & 31;
    const int w = tid >> 5;
    const int blockBase = blockIdx.x * ELTS;
    char* xwarp = Xs + (size_t)(w << 5) * ROWB;

    // ---- per-CTA b-frag table: thread tid packs slots 3*tid .. 3*tid+2 ----
    // slot g: lane L = g/12, q = g%12; s = q%6; B1 if q>=6.
    // B0[s] = {w1[bn*96+k0], +1}*sc ; B1[s] = {+8, +9}*sc ; k0 = 16s+2bk,
    // sc = 1/64 for s<4 (um & u regions), 1 for s>=4 (m region).
#pragma unroll
    for (int r = 0; r < 3; ++r) {
        const int g = 3 * tid + r;
        const int L = g / 12, q = g - 12 * L;
        const int s = (q >= 6) ? q - 6 : q;
        const int k0 = 16 * s + 2 * (L & 3) + ((q >= 6) ? 8 : 0);
        const float sc = (s < 4) ? U_INV : 1.0f;
        const float* wr = w1 + (L >> 2) * 96 + k0;
        fragS[g] = packh2(__ldg(wr) * sc, __ldg(wr + 1) * sc);
    }
    if (tid < 8) { biasS[tid] = __ldg(&b1[tid]); biasS[8 + tid] = __ldg(&w2[tid]); }
    if (tid == 0) biasS[16] = __ldg(&b2[0]);

    // ---- cooperative coalesced gather, 2-deep pipelined ----
    int eg = blockBase + (w << 5) + l;
    int ec = (eg < n) ? eg : (n - 1);
    const int uidx = users[ec];
    const int midx = movies[ec];

    const int chunk = l & 7;     // 16B chunk of the 128B embedding row
    const int esub = l >> 3;     // 0..3

    {
        float4 u4a, m4a;
        {
            const int ue = __shfl_sync(FULL, uidx, esub);
            const int me = __shfl_sync(FULL, midx, esub);
            u4a = ldg_na128(user_emb + (size_t)ue * 32 + (chunk << 2));
            m4a = ldg_na128(movie_emb + (size_t)me * 32 + (chunk << 2));
        }
#pragma unroll
        for (int i = 0; i < 8; ++i) {
            float4 u4 = u4a, m4 = m4a;
            if (i < 7) {
                const int src = 4 * (i + 1) + esub;
                const int ue = __shfl_sync(FULL, uidx, src);
                const int me = __shfl_sync(FULL, midx, src);
                u4a = ldg_na128(user_emb + (size_t)ue * 32 + (chunk << 2));
                m4a = ldg_na128(movie_emb + (size_t)me * 32 + (chunk << 2));
            }
            char* xr = xwarp + (size_t)(4 * i + esub) * ROWB + (chunk << 3);
            *(uint2*)(xr) = make_uint2(packh2(u4.x * U_SCALE, u4.y * U_SCALE),
                                       packh2(u4.z * U_SCALE, u4.w * U_SCALE));
            *(uint2*)(xr + 64) = make_uint2(packh2(m4.x, m4.y), packh2(m4.z, m4.w));
        }
    }

    __syncthreads();   // frag table + X tile both ready

    // ---- per-thread frags: 3x LDS.128, conflict-free (48B lane stride) ----
    uint32_t B0[6], B1[6];
    {
        const uint4* fp = (const uint4*)(fragS + l * 12);
        uint4 F0 = fp[0], F1 = fp[1], F2 = fp[2];
        B0[0] = F0.x; B0[1] = F0.y; B0[2] = F0.z; B0[3] = F0.w;
        B0[4] = F1.x; B0[5] = F1.y; B1[0] = F1.z; B1[1] = F1.w;
        B1[2] = F2.x; B1[3] = F2.y; B1[4] = F2.z; B1[5] = F2.w;
    }

    // ---- GEMM: 2 m-tiles; u,m frags via ldmatrix, um frags via hmul2 ----
    const uint32_t xs = (uint32_t)__cvta_generic_to_shared(xwarp);
    float acc[2][4] = {{0.f, 0.f, 0.f, 0.f}, {0.f, 0.f, 0.f, 0.f}};

#pragma unroll
    for (int t = 0; t < 2; ++t) {
        const uint32_t abase = xs + (uint32_t)((t * 16 + (l & 15)) * ROWB)
                             + (uint32_t)((l >> 4) << 4);
        uint32_t U[2][4], M[2][4];
        ldsm4(U[0], abase);
        ldsm4(U[1], abase + 32);
        ldsm4(M[0], abase + 64);
        ldsm4(M[1], abase + 96);

        uint32_t P[4];
#pragma unroll
        for (int j = 0; j < 4; ++j) P[j] = hmul2u(U[0][j], M[0][j]);
        mma_f16(acc[t], P[0], P[1], P[2], P[3], B0[0], B1[0]);
#pragma unroll
        for (int j = 0; j < 4; ++j) P[j] = hmul2u(U[1][j], M[1][j]);
        mma_f16(acc[t], P[0], P[1], P[2], P[3], B0[1], B1[1]);

        mma_f16(acc[t], U[0][0], U[0][1], U[0][2], U[0][3], B0[2], B1[2]);
        mma_f16(acc[t], U[1][0], U[1][1], U[1][2], U[1][3], B0[3], B1[3]);
        mma_f16(acc[t], M[0][0], M[0][1], M[0][2], M[0][3], B0[4], B1[4]);
        mma_f16(acc[t], M[1][0], M[1][1], M[1][2], M[1][3], B0[5], B1[5]);
    }

    // ---- epilogue: relu+bias, dot w2 across quad, sigmoid ----
    const int bk = l & 3;
    const float b1a = biasS[2 * bk];
    const float b1b = biasS[2 * bk + 1];
    const float w2a = biasS[8 + 2 * bk];
    const float w2b = biasS[9 + 2 * bk];
    const float bb2 = biasS[16];

#pragma unroll
    for (int t = 0; t < 2; ++t) {
        float z0 = fmaxf(acc[t][0] + b1a, 0.f) * w2a +
                   fmaxf(acc[t][1] + b1b, 0.f) * w2b;
        float z1 = fmaxf(acc[t][2] + b1a, 0.f) * w2a +
                   fmaxf(acc[t][3] + b1b, 0.f) * w2b;
        z0 += __shfl_xor_sync(FULL, z0, 1);
        z0 += __shfl_xor_sync(FULL, z0, 2);
        z1 += __shfl_xor_sync(FULL, z1, 1);
        z1 += __shfl_xor_sync(FULL, z1, 2);
        if (bk == 0) {
            const int e0 = blockBase + (w << 5) + t * 16 + (l >> 2);
            if (e0 < n) out[e0] = 1.0f / (1.0f + __expf(-(z0 + bb2)));
            const int e1 = e0 + 8;
            if (e1 < n) out[e1] = 1.0f / (1.0f + __expf(-(z1 + bb2)));
        }
    }
}

extern "C" void kernel_launch(void* const* d_in, const int* in_sizes, int n_in,
                              void* d_out, int out_size) {
    const int*   users     = (const int*)d_in[0];
    const int*   movies    = (const int*)d_in[1];
    const float* user_emb  = (const float*)d_in[2];
    const float* movie_emb = (const float*)d_in[3];
    const float* w1        = (const float*)d_in[4];
    const float* b1        = (const float*)d_in[5];
    const float* w2        = (const float*)d_in[6];
    const float* b2        = (const float*)d_in[7];
    int n = in_sizes[0];

    int blocks = (n + ELTS - 1) / ELTS;
    neuralnet_mma16e_kernel<<<blocks, NTHREADS, SMEM_TOTAL>>>(
        users, movies, user_emb, movie_emb, w1, b1, w2, b2, (float*)d_out, n);
}

// round 9
// speedup vs baseline: 2.4080x; 1.1490x over previous
#include <cuda_runtime.h>
#include <cuda_fp16.h>
#include <cstdint>
#include <cstddef>

// x = [u*m, u, m] (96) ; h = relu(x @ w1^T + b1) (8) ; out = sigmoid(h @ w2^T + b2)
// D = X@W1^T via mma.sync.m16n8k16 fp16 (fp32 accum); [64u|m] SMEM tile;
// um a-frags = hmul2(u,m) in regs; b-frag k-steps 0..3 carry 1/64.
// R9: (a) frag table read BEFORE gather; only __syncwarp after gather -> warps
// fully independent through the latency-heavy phase; (b) 256-thread CTAs
// (halve table-build + CTA count), 5 CTAs/SM -> same 40 warps/SM.

#define NTHREADS 256
#define ELTS 256
#define ROWB 144            // 64B u + 64B m + 16B pad
#define U_SCALE 64.0f
#define U_INV (1.0f / 64.0f)

#define XS_BYTES (ELTS * ROWB)        // 36864
#define FRAG_OFF XS_BYTES             // uint32_t[384]: [lane][12] = [B0[0..5], B1[0..5]]
#define BIAS_OFF (FRAG_OFF + 1536)    // float[17]
#define SMEM_TOTAL (BIAS_OFF + 128)   // 38528 -> 5 CTAs/SM

__device__ __forceinline__ float4 ldg_na128(const float* p) {
    float4 v;
    asm volatile("ld.global.L1::no_allocate.v4.f32 {%0,%1,%2,%3}, [%4];"
                 : "=f"(v.x), "=f"(v.y), "=f"(v.z), "=f"(v.w) : "l"(p));
    return v;
}

__device__ __forceinline__ uint32_t packh2(float a, float b) {
    __half2 h = __floats2half2_rn(a, b);
    return *(uint32_t*)&h;
}

__device__ __forceinline__ uint32_t hmul2u(uint32_t a, uint32_t b) {
    __half2 r = __hmul2(*(__half2*)&a, *(__half2*)&b);
    return *(uint32_t*)&r;
}

__device__ __forceinline__ void mma_f16(float* c, uint32_t a0, uint32_t a1,
                                        uint32_t a2, uint32_t a3,
                                        uint32_t b0, uint32_t b1) {
    asm volatile(
        "mma.sync.aligned.m16n8k16.row.col.f32.f16.f16.f32 "
        "{%0,%1,%2,%3}, {%4,%5,%6,%7}, {%8,%9}, {%0,%1,%2,%3};"
        : "+f"(c[0]), "+f"(c[1]), "+f"(c[2]), "+f"(c[3])
        : "r"(a0), "r"(a1), "r"(a2), "r"(a3), "r"(b0), "r"(b1));
}

__device__ __forceinline__ void ldsm4(uint32_t* r, uint32_t addr) {
    asm volatile("ldmatrix.sync.aligned.m8n8.x4.shared.b16 {%0,%1,%2,%3}, [%4];"
                 : "=r"(r[0]), "=r"(r[1]), "=r"(r[2]), "=r"(r[3]) : "r"(addr));
}

__global__ __launch_bounds__(NTHREADS, 5)
void neuralnet_mma16f_kernel(const int* __restrict__ users,
                             const int* __restrict__ movies,
                             const float* __restrict__ user_emb,
                             const float* __restrict__ movie_emb,
                             const float* __restrict__ w1,
                             const float* __restrict__ b1,
                             const float* __restrict__ w2,
                             const float* __restrict__ b2,
                             float* __restrict__ out,
                             int n) {
    extern __shared__ __align__(16) char Xs[];
    uint32_t* fragS = (uint32_t*)(Xs + FRAG_OFF);
    float* biasS = (float*)(Xs + BIAS_OFF);

    const unsigned FULL = 0xffffffffu;
    const int tid = threadIdx.x;
    const int l = tid & 31;
    const int w = tid >> 5;
    const int blockBase = blockIdx.x * ELTS;
    char* xwarp = Xs + (size_t)(w << 5) * ROWB;

    // ---- per-CTA b-frag table: threads 0..127 pack 3 slots each ----
    if (tid < 128) {
#pragma unroll
        for (int r = 0; r < 3; ++r) {
            const int g = 3 * tid + r;
            const int L = g / 12, q = g - 12 * L;
            const int s = (q >= 6) ? q - 6 : q;
            const int k0 = 16 * s + 2 * (L & 3) + ((q >= 6) ? 8 : 0);
            const float sc = (s < 4) ? U_INV : 1.0f;
            const float* wr = w1 + (L >> 2) * 96 + k0;
            fragS[g] = packh2(__ldg(wr) * sc, __ldg(wr + 1) * sc);
        }
    } else if (tid < 136) {
        const int i = tid - 128;
        biasS[i] = __ldg(&b1[i]);
        biasS[8 + i] = __ldg(&w2[i]);
        if (i == 0) biasS[16] = __ldg(&b2[0]);
    }
    __syncthreads();   // early, uniform convergence point (nothing heavy yet)

    // ---- per-thread frags + biases into regs (3 conflict-free LDS.128) ----
    uint32_t B0[6], B1[6];
    {
        const uint4* fp = (const uint4*)(fragS + l * 12);
        uint4 F0 = fp[0], F1 = fp[1], F2 = fp[2];
        B0[0] = F0.x; B0[1] = F0.y; B0[2] = F0.z; B0[3] = F0.w;
        B0[4] = F1.x; B0[5] = F1.y; B1[0] = F1.z; B1[1] = F1.w;
        B1[2] = F2.x; B1[3] = F2.y; B1[4] = F2.z; B1[5] = F2.w;
    }
    const int bk = l & 3;
    const float b1a = biasS[2 * bk];
    const float b1b = biasS[2 * bk + 1];
    const float w2a = biasS[8 + 2 * bk];
    const float w2b = biasS[9 + 2 * bk];
    const float bb2 = biasS[16];

    // ---- cooperative coalesced gather, 2-deep pipelined (warp-private) ----
    int eg = blockBase + (w << 5) + l;
    int ec = (eg < n) ? eg : (n - 1);
    const int uidx = users[ec];
    const int midx = movies[ec];

    const int chunk = l & 7;
    const int esub = l >> 3;

    {
        float4 u4a, m4a;
        {
            const int ue = __shfl_sync(FULL, uidx, esub);
            const int me = __shfl_sync(FULL, midx, esub);
            u4a = ldg_na128(user_emb + (size_t)ue * 32 + (chunk << 2));
            m4a = ldg_na128(movie_emb + (size_t)me * 32 + (chunk << 2));
        }
#pragma unroll
        for (int i = 0; i < 8; ++i) {
            float4 u4 = u4a, m4 = m4a;
            if (i < 7) {
                const int src = 4 * (i + 1) + esub;
                const int ue = __shfl_sync(FULL, uidx, src);
                const int me = __shfl_sync(FULL, midx, src);
                u4a = ldg_na128(user_emb + (size_t)ue * 32 + (chunk << 2));
                m4a = ldg_na128(movie_emb + (size_t)me * 32 + (chunk << 2));
            }
            char* xr = xwarp + (size_t)(4 * i + esub) * ROWB + (chunk << 3);
            *(uint2*)(xr) = make_uint2(packh2(u4.x * U_SCALE, u4.y * U_SCALE),
                                       packh2(u4.z * U_SCALE, u4.w * U_SCALE));
            *(uint2*)(xr + 64) = make_uint2(packh2(m4.x, m4.y), packh2(m4.z, m4.w));
        }
    }
    __syncwarp();   // warp-private tile: no CTA-wide barrier needed

    // ---- GEMM: 2 m-tiles; u,m frags via ldmatrix, um frags via hmul2 ----
    const uint32_t xs = (uint32_t)__cvta_generic_to_shared(xwarp);
    float acc[2][4] = {{0.f, 0.f, 0.f, 0.f}, {0.f, 0.f, 0.f, 0.f}};

#pragma unroll
    for (int t = 0; t < 2; ++t) {
        const uint32_t abase = xs + (uint32_t)((t * 16 + (l & 15)) * ROWB)
                             + (uint32_t)((l >> 4) << 4);
        uint32_t U[2][4], M[2][4];
        ldsm4(U[0], abase);
        ldsm4(U[1], abase + 32);
        ldsm4(M[0], abase + 64);
        ldsm4(M[1], abase + 96);

        uint32_t P[4];
#pragma unroll
        for (int j = 0; j < 4; ++j) P[j] = hmul2u(U[0][j], M[0][j]);
        mma_f16(acc[t], P[0], P[1], P[2], P[3], B0[0], B1[0]);
#pragma unroll
        for (int j = 0; j < 4; ++j) P[j] = hmul2u(U[1][j], M[1][j]);
        mma_f16(acc[t], P[0], P[1], P[2], P[3], B0[1], B1[1]);

        mma_f16(acc[t], U[0][0], U[0][1], U[0][2], U[0][3], B0[2], B1[2]);
        mma_f16(acc[t], U[1][0], U[1][1], U[1][2], U[1][3], B0[3], B1[3]);
        mma_f16(acc[t], M[0][0], M[0][1], M[0][2], M[0][3], B0[4], B1[4]);
        mma_f16(acc[t], M[1][0], M[1][1], M[1][2], M[1][3], B0[5], B1[5]);
    }

    // ---- epilogue: relu+bias, dot w2 across quad, sigmoid ----
#pragma unroll
    for (int t = 0; t < 2; ++t) {
        float z0 = fmaxf(acc[t][0] + b1a, 0.f) * w2a +
                   fmaxf(acc[t][1] + b1b, 0.f) * w2b;
        float z1 = fmaxf(acc[t][2] + b1a, 0.f) * w2a +
                   fmaxf(acc[t][3] + b1b, 0.f) * w2b;
        z0 += __shfl_xor_sync(FULL, z0, 1);
        z0 += __shfl_xor_sync(FULL, z0, 2);
        z1 += __shfl_xor_sync(FULL, z1, 1);
        z1 += __shfl_xor_sync(FULL, z1, 2);
        if (bk == 0) {
            const int e0 = blockBase + (w << 5) + t * 16 + (l >> 2);
            if (e0 < n) out[e0] = 1.0f / (1.0f + __expf(-(z0 + bb2)));
            const int e1 = e0 + 8;
            if (e1 < n) out[e1] = 1.0f / (1.0f + __expf(-(z1 + bb2)));
        }
    }
}

extern "C" void kernel_launch(void* const* d_in, const int* in_sizes, int n_in,
                              void* d_out, int out_size) {
    const int*   users     = (const int*)d_in[0];
    const int*   movies    = (const int*)d_in[1];
    const float* user_emb  = (const float*)d_in[2];
    const float* movie_emb = (const float*)d_in[3];
    const float* w1        = (const float*)d_in[4];
    const float* b1        = (const float*)d_in[5];
    const float* w2        = (const float*)d_in[6];
    const float* b2        = (const float*)d_in[7];
    int n = in_sizes[0];

    static bool attr_set = false;
    if (!attr_set) {
        cudaFuncSetAttribute(neuralnet_mma16f_kernel,
                             cudaFuncAttributeMaxDynamicSharedMemorySize, SMEM_TOTAL);
        attr_set = true;
    }
    int blocks = (n + ELTS - 1) / ELTS;
    neuralnet_mma16f_kernel<<<blocks, NTHREADS, SMEM_TOTAL>>>(
        users, movies, user_emb, movie_emb, w1, b1, w2, b2, (float*)d_out, n);
}

// round 10
// speedup vs baseline: 2.6452x; 1.0985x over previous
#include <cuda_runtime.h>
#include <cuda_fp16.h>
#include <cstdint>
#include <cstddef>

// x = [u*m, u, m] (96) ; h = relu(x @ w1^T + b1) (8) ; out = sigmoid(h @ w2^T + b2)
// D = X@W1^T via mma.sync.m16n8k16 fp16 (fp32 accum); [64u|m] SMEM tile;
// um a-frags = hmul2(u,m) in regs; b-frag k-steps 0..3 carry 1/64.
// R10: B-frag/bias loads moved AFTER the gather (frees ~17 live regs there);
// gather deepened to a 4-stage pipeline (MLP=8) within the freed budget.

#define NTHREADS 256
#define ELTS 256
#define ROWB 144            // 64B u + 64B m + 16B pad
#define U_SCALE 64.0f
#define U_INV (1.0f / 64.0f)

#define XS_BYTES (ELTS * ROWB)        // 36864
#define FRAG_OFF XS_BYTES             // uint32_t[384]: [lane][12]
#define BIAS_OFF (FRAG_OFF + 1536)    // float[17]
#define SMEM_TOTAL (BIAS_OFF + 128)   // 38528 -> 5 CTAs/SM

__device__ __forceinline__ float4 ldg_na128(const float* p) {
    float4 v;
    asm volatile("ld.global.L1::no_allocate.v4.f32 {%0,%1,%2,%3}, [%4];"
                 : "=f"(v.x), "=f"(v.y), "=f"(v.z), "=f"(v.w) : "l"(p));
    return v;
}

__device__ __forceinline__ uint32_t packh2(float a, float b) {
    __half2 h = __floats2half2_rn(a, b);
    return *(uint32_t*)&h;
}

__device__ __forceinline__ uint32_t hmul2u(uint32_t a, uint32_t b) {
    __half2 r = __hmul2(*(__half2*)&a, *(__half2*)&b);
    return *(uint32_t*)&r;
}

__device__ __forceinline__ void mma_f16(float* c, uint32_t a0, uint32_t a1,
                                        uint32_t a2, uint32_t a3,
                                        uint32_t b0, uint32_t b1) {
    asm volatile(
        "mma.sync.aligned.m16n8k16.row.col.f32.f16.f16.f32 "
        "{%0,%1,%2,%3}, {%4,%5,%6,%7}, {%8,%9}, {%0,%1,%2,%3};"
        : "+f"(c[0]), "+f"(c[1]), "+f"(c[2]), "+f"(c[3])
        : "r"(a0), "r"(a1), "r"(a2), "r"(a3), "r"(b0), "r"(b1));
}

__device__ __forceinline__ void ldsm4(uint32_t* r, uint32_t addr) {
    asm volatile("ldmatrix.sync.aligned.m8n8.x4.shared.b16 {%0,%1,%2,%3}, [%4];"
                 : "=r"(r[0]), "=r"(r[1]), "=r"(r[2]), "=r"(r[3]) : "r"(addr));
}

__global__ __launch_bounds__(NTHREADS, 5)
void neuralnet_mma16g_kernel(const int* __restrict__ users,
                             const int* __restrict__ movies,
                             const float* __restrict__ user_emb,
                             const float* __restrict__ movie_emb,
                             const float* __restrict__ w1,
                             const float* __restrict__ b1,
                             const float* __restrict__ w2,
                             const float* __restrict__ b2,
                             float* __restrict__ out,
                             int n) {
    extern __shared__ __align__(16) char Xs[];
    uint32_t* fragS = (uint32_t*)(Xs + FRAG_OFF);
    float* biasS = (float*)(Xs + BIAS_OFF);

    const unsigned FULL = 0xffffffffu;
    const int tid = threadIdx.x;
    const int l = tid & 31;
    const int w = tid >> 5;
    const int blockBase = blockIdx.x * ELTS;
    char* xwarp = Xs + (size_t)(w << 5) * ROWB;

    // ---- per-CTA b-frag table: threads 0..127 pack 3 slots each ----
    if (tid < 128) {
#pragma unroll
        for (int r = 0; r < 3; ++r) {
            const int g = 3 * tid + r;
            const int L = g / 12, q = g - 12 * L;
            const int s = (q >= 6) ? q - 6 : q;
            const int k0 = 16 * s + 2 * (L & 3) + ((q >= 6) ? 8 : 0);
            const float sc = (s < 4) ? U_INV : 1.0f;
            const float* wr = w1 + (L >> 2) * 96 + k0;
            fragS[g] = packh2(__ldg(wr) * sc, __ldg(wr + 1) * sc);
        }
    } else if (tid < 136) {
        const int i = tid - 128;
        biasS[i] = __ldg(&b1[i]);
        biasS[8 + i] = __ldg(&w2[i]);
        if (i == 0) biasS[16] = __ldg(&b2[0]);
    }
    __syncthreads();   // early, uniform convergence; nothing heavy before it

    // ---- cooperative coalesced gather, 4-deep pipeline (MLP=8) ----
    int eg = blockBase + (w << 5) + l;
    int ec = (eg < n) ? eg : (n - 1);
    const int uidx = users[ec];
    const int midx = movies[ec];

    const int chunk = l & 7;
    const int esub = l >> 3;
    const float* uC = user_emb + (chunk << 2);
    const float* mC = movie_emb + (chunk << 2);

    {
        float4 ub[4], mb[4];
#pragma unroll
        for (int i = 0; i < 4; ++i) {
            const int src = 4 * i + esub;
            const int ue = __shfl_sync(FULL, uidx, src);
            const int me = __shfl_sync(FULL, midx, src);
            ub[i] = ldg_na128(uC + (size_t)ue * 32);
            mb[i] = ldg_na128(mC + (size_t)me * 32);
        }
#pragma unroll
        for (int i = 0; i < 8; ++i) {
            const float4 u4 = ub[i & 3];
            const float4 m4 = mb[i & 3];
            if (i < 4) {
                const int src = 4 * (i + 4) + esub;
                const int ue = __shfl_sync(FULL, uidx, src);
                const int me = __shfl_sync(FULL, midx, src);
                ub[i & 3] = ldg_na128(uC + (size_t)ue * 32);
                mb[i & 3] = ldg_na128(mC + (size_t)me * 32);
            }
            char* xr = xwarp + (size_t)(4 * i + esub) * ROWB + (chunk << 3);
            *(uint2*)(xr) = make_uint2(packh2(u4.x * U_SCALE, u4.y * U_SCALE),
                                       packh2(u4.z * U_SCALE, u4.w * U_SCALE));
            *(uint2*)(xr + 64) = make_uint2(packh2(m4.x, m4.y), packh2(m4.z, m4.w));
        }
    }
    __syncwarp();   // warp-private tile

    // ---- per-thread frags (3 conflict-free LDS.128), AFTER gather ----
    uint32_t B0[6], B1[6];
    {
        const uint4* fp = (const uint4*)(fragS + l * 12);
        uint4 F0 = fp[0], F1 = fp[1], F2 = fp[2];
        B0[0] = F0.x; B0[1] = F0.y; B0[2] = F0.z; B0[3] = F0.w;
        B0[4] = F1.x; B0[5] = F1.y; B1[0] = F1.z; B1[1] = F1.w;
        B1[2] = F2.x; B1[3] = F2.y; B1[4] = F2.z; B1[5] = F2.w;
    }

    // ---- GEMM: 2 m-tiles; u,m frags via ldmatrix, um frags via hmul2 ----
    const uint32_t xs = (uint32_t)__cvta_generic_to_shared(xwarp);
    float acc[2][4] = {{0.f, 0.f, 0.f, 0.f}, {0.f, 0.f, 0.f, 0.f}};

#pragma unroll
    for (int t = 0; t < 2; ++t) {
        const uint32_t abase = xs + (uint32_t)((t * 16 + (l & 15)) * ROWB)
                             + (uint32_t)((l >> 4) << 4);
        uint32_t U[2][4], M[2][4];
        ldsm4(U[0], abase);
        ldsm4(U[1], abase + 32);
        ldsm4(M[0], abase + 64);
        ldsm4(M[1], abase + 96);

        uint32_t P[4];
#pragma unroll
        for (int j = 0; j < 4; ++j) P[j] = hmul2u(U[0][j], M[0][j]);
        mma_f16(acc[t], P[0], P[1], P[2], P[3], B0[0], B1[0]);
#pragma unroll
        for (int j = 0; j < 4; ++j) P[j] = hmul2u(U[1][j], M[1][j]);
        mma_f16(acc[t], P[0], P[1], P[2], P[3], B0[1], B1[1]);

        mma_f16(acc[t], U[0][0], U[0][1], U[0][2], U[0][3], B0[2], B1[2]);
        mma_f16(acc[t], U[1][0], U[1][1], U[1][2], U[1][3], B0[3], B1[3]);
        mma_f16(acc[t], M[0][0], M[0][1], M[0][2], M[0][3], B0[4], B1[4]);
        mma_f16(acc[t], M[1][0], M[1][1], M[1][2], M[1][3], B0[5], B1[5]);
    }

    // ---- epilogue: biases read here (not held across the body) ----
    const int bk = l & 3;
    const float b1a = biasS[2 * bk];
    const float b1b = biasS[2 * bk + 1];
    const float w2a = biasS[8 + 2 * bk];
    const float w2b = biasS[9 + 2 * bk];
    const float bb2 = biasS[16];

#pragma unroll
    for (int t = 0; t < 2; ++t) {
        float z0 = fmaxf(acc[t][0] + b1a, 0.f) * w2a +
                   fmaxf(acc[t][1] + b1b, 0.f) * w2b;
        float z1 = fmaxf(acc[t][2] + b1a, 0.f) * w2a +
                   fmaxf(acc[t][3] + b1b, 0.f) * w2b;
        z0 += __shfl_xor_sync(FULL, z0, 1);
        z0 += __shfl_xor_sync(FULL, z0, 2);
        z1 += __shfl_xor_sync(FULL, z1, 1);
        z1 += __shfl_xor_sync(FULL, z1, 2);
        if (bk == 0) {
            const int e0 = blockBase + (w << 5) + t * 16 + (l >> 2);
            if (e0 < n) out[e0] = 1.0f / (1.0f + __expf(-(z0 + bb2)));
            const int e1 = e0 + 8;
            if (e1 < n) out[e1] = 1.0f / (1.0f + __expf(-(z1 + bb2)));
        }
    }
}

extern "C" void kernel_launch(void* const* d_in, const int* in_sizes, int n_in,
                              void* d_out, int out_size) {
    const int*   users     = (const int*)d_in[0];
    const int*   movies    = (const int*)d_in[1];
    const float* user_emb  = (const float*)d_in[2];
    const float* movie_emb = (const float*)d_in[3];
    const float* w1        = (const float*)d_in[4];
    const float* b1        = (const float*)d_in[5];
    const float* w2        = (const float*)d_in[6];
    const float* b2        = (const float*)d_in[7];
    int n = in_sizes[0];

    static bool attr_set = false;
    if (!attr_set) {
        cudaFuncSetAttribute(neuralnet_mma16g_kernel,
                             cudaFuncAttributeMaxDynamicSharedMemorySize, SMEM_TOTAL);
        attr_set = true;
    }
    int blocks = (n + ELTS - 1) / ELTS;
    neuralnet_mma16g_kernel<<<blocks, NTHREADS, SMEM_TOTAL>>>(
        users, movies, user_emb, movie_emb, w1, b1, w2, b2, (float*)d_out, n);
}